// round 3
// baseline (speedup 1.0000x reference)
#include <cuda_runtime.h>
#include <math.h>

#define L_    128
#define H2_   600
#define P_    50
#define A_    50
#define AP_   64
#define T_    3
#define K_    700     // H2 + 2P
#define KC_   16
#define NCH_  44      // ceil(704/16) -> padded K=704
#define MAXB  2048
#define XPITCH 132    // 128 + 4 pad
#define WPITCH 68     // 64 + 4 pad

__device__ float g_u2[MAXB * AP_];
__device__ float g_c[2][T_][AP_];   // precomputed latent_t . W_ent block{1,3}

typedef unsigned long long ull;

__device__ __forceinline__ ull pack2(float lo, float hi) {
    ull r;
    asm("mov.b64 %0, {%1, %2};" : "=l"(r) : "f"(lo), "f"(hi));
    return r;
}
__device__ __forceinline__ void unpack2(ull v, float& lo, float& hi) {
    asm("mov.b64 {%0, %1}, %2;" : "=f"(lo), "=f"(hi) : "l"(v));
}
__device__ __forceinline__ void fma2(ull& d, ull a, ull b) {
    asm("fma.rn.f32x2 %0, %1, %2, %0;" : "+l"(d) : "l"(a), "l"(b));
}

// W smem chunk permutation: a = g*4+s (g=0..15); pgroup = (g&1)*8 + (g>>1)
// -> thread tx reads its 8 a's (groups 2tx,2tx+1) as two contiguous-128B LDS.128
__device__ __forceinline__ int wpos(int a) {
    int g = a >> 2, s = a & 3;
    return (((g & 1) << 3) + (g >> 1)) * 4 + s;
}

// ---------------------------------------------------------------------------
// k_prep: c[which][t][a] = sum_d latent[t][d] * W_ent[a][(1 + 2*which)*600 + d]
// 300 tasks, one warp each.
// ---------------------------------------------------------------------------
__global__ void k_prep(const float* __restrict__ W_ent,
                       const float* __restrict__ latent) {
    int w = blockIdx.x * (blockDim.x >> 5) + (threadIdx.x >> 5);
    int lane = threadIdx.x & 31;
    if (w >= 300) return;
    int which = w / 150;
    int rem   = w % 150;
    int t = rem / A_;
    int a = rem % A_;
    const float* Wr = W_ent + (size_t)a * (4 * H2_) + (1 + 2 * which) * H2_;
    const float* lt = latent + (size_t)t * H2_;
    float s = 0.f;
    for (int d = lane; d < H2_; d += 32) s += Wr[d] * lt[d];
    for (int o = 16; o; o >>= 1) s += __shfl_xor_sync(0xffffffffu, s, o);
    if (lane == 0) g_c[which][t][a] = s;
}

// ---------------------------------------------------------------------------
// k_entity: u2[b, a] = W_ent1.he1 + W_ent3.he2 + sum_t a1_t c1[t][a] + a2_t c2[t][a]
// ---------------------------------------------------------------------------
__global__ void __launch_bounds__(256) k_entity(
    const float* __restrict__ hidden,
    const int*   __restrict__ e1_idx,
    const int*   __restrict__ e2_idx,
    const float* __restrict__ W_ent,
    const float* __restrict__ latent)
{
    int b   = blockIdx.x;
    int tid = threadIdx.x;
    __shared__ float he1[H2_], he2[H2_];
    __shared__ float dots[6];

    const float* h1 = hidden + ((size_t)b * L_ + e1_idx[b]) * H2_;
    const float* h2 = hidden + ((size_t)b * L_ + e2_idx[b]) * H2_;
    for (int d = tid; d < H2_; d += blockDim.x) { he1[d] = h1[d]; he2[d] = h2[d]; }
    __syncthreads();

    int w = tid >> 5, lane = tid & 31;
    if (w < 6) {
        const float* ent = (w < 3) ? he1 : he2;
        const float* lt  = latent + (w % 3) * H2_;
        float s = 0.f;
        for (int d = lane; d < H2_; d += 32) s += ent[d] * lt[d];
        for (int o = 16; o; o >>= 1) s += __shfl_xor_sync(0xffffffffu, s, o);
        if (lane == 0) dots[w] = s;
    }
    __syncthreads();

    float a10, a11, a12, a20, a21, a22;
    {
        float m  = fmaxf(dots[0], fmaxf(dots[1], dots[2]));
        float e0 = expf(dots[0] - m), e1 = expf(dots[1] - m), e2 = expf(dots[2] - m);
        float inv = 1.f / (e0 + e1 + e2);
        a10 = e0 * inv; a11 = e1 * inv; a12 = e2 * inv;
        m  = fmaxf(dots[3], fmaxf(dots[4], dots[5]));
        e0 = expf(dots[3] - m); e1 = expf(dots[4] - m); e2 = expf(dots[5] - m);
        inv = 1.f / (e0 + e1 + e2);
        a20 = e0 * inv; a21 = e1 * inv; a22 = e2 * inv;
    }

    for (int a = w; a < A_; a += 8) {
        const float* Wr = W_ent + (size_t)a * (4 * H2_);
        float s = 0.f;
        for (int d = lane; d < H2_; d += 32) {
            s += Wr[d]             * he1[d];
            s += Wr[2 * H2_ + d]   * he2[d];
        }
        for (int o = 16; o; o >>= 1) s += __shfl_xor_sync(0xffffffffu, s, o);
        if (lane == 0) {
            s += a10 * g_c[0][0][a] + a11 * g_c[0][1][a] + a12 * g_c[0][2][a];
            s += a20 * g_c[1][0][a] + a21 * g_c[1][1][a] + a22 * g_c[1][2][a];
            g_u2[b * AP_ + a] = s;
        }
    }
    if (tid >= A_ && tid < AP_) g_u2[b * AP_ + tid] = 0.f;
}

// ---------------------------------------------------------------------------
// k_main: 128 threads, per-thread tile 8L x 8A (packed f32x2 over L-pairs).
// tx = tid&7  -> a = tx*8 + 0..7
// ty = tid>>3 -> l = 4*ty + {0,1,2,3} and 4*ty + 64 + {0,1,2,3}
// ---------------------------------------------------------------------------
__global__ void __launch_bounds__(128) k_main(
    const float* __restrict__ hidden,  // [B, L, H2]
    const float* __restrict__ pos1,    // [B, L, P]
    const float* __restrict__ pos2,    // [B, L, P]
    const float* __restrict__ W_hid,   // [A, K]
    const float* __restrict__ v,       // [A, 1]
    float*       __restrict__ out)     // [B, H2]
{
    __shared__ __align__(16) float Xs[2][KC_][XPITCH];
    __shared__ __align__(16) float Ws[2][KC_][WPITCH];
    __shared__ float sp[8][L_ + 1];
    __shared__ float alpha[L_];
    __shared__ float u2s[AP_], vs[AP_];
    __shared__ float redm[4], reds[4];

    int b   = blockIdx.x;
    int tid = threadIdx.x;
    int tx  = tid & 7;
    int ty  = tid >> 3;

    if (tid < AP_) {
        u2s[tid] = g_u2[b * AP_ + tid];
        vs[tid]  = (tid < A_) ? v[tid] : 0.f;
    }

    const float* hb  = hidden + (size_t)b * L_ * H2_;
    const float* p1b = pos1   + (size_t)b * L_ * P_;
    const float* p2b = pos2   + (size_t)b * L_ * P_;

    // X loader: thread tid owns l-row tid, loads 16 consecutive k
    const float* hrow = hb  + (size_t)tid * H2_;
    const float* p1r  = p1b + (size_t)tid * P_;
    const float* p2r  = p2b + (size_t)tid * P_;
    // W loader: wa = tid&63, wkh = tid>>6 (k-half), permuted position
    const int wa  = tid & 63;
    const int wkh = (tid >> 6) * 8;
    const int wp  = wpos(wa);

    auto loadX = [&](int c, int buf) {
        int kb = c * KC_;
        #pragma unroll
        for (int j = 0; j < KC_; j++) {
            int k = kb + j;
            float val;
            if      (k < H2_)       val = hrow[k];
            else if (k < H2_ + P_)  val = p1r[k - H2_];
            else if (k < K_)        val = p2r[k - H2_ - P_];
            else                    val = 0.f;
            Xs[buf][j][tid] = val;
        }
    };
    auto loadW = [&](int c, int buf) {
        int kb = c * KC_;
        #pragma unroll
        for (int j = 0; j < 8; j++) {
            int k = kb + wkh + j;
            float val = (wa < A_ && k < K_) ? W_hid[(size_t)wa * K_ + k] : 0.f;
            Ws[buf][wkh + j][wp] = val;
        }
    };

    ull acc[4][8];
    #pragma unroll
    for (int i = 0; i < 4; i++)
        #pragma unroll
        for (int j = 0; j < 8; j++) acc[i][j] = 0ull;

    loadX(0, 0); loadW(0, 0);
    __syncthreads();

    for (int c = 0; c < NCH_; c++) {
        int buf = c & 1;
        if (c + 1 < NCH_) { loadX(c + 1, buf ^ 1); loadW(c + 1, buf ^ 1); }
        #pragma unroll
        for (int kk = 0; kk < KC_; kk++) {
            // W: two conflict-free LDS.128 (permuted layout), then broadcast-pack
            float4 wlo = *(const float4*)&Ws[buf][kk][tx * 4];
            float4 whi = *(const float4*)&Ws[buf][kk][32 + tx * 4];
            ull w2[8];
            w2[0] = pack2(wlo.x, wlo.x); w2[1] = pack2(wlo.y, wlo.y);
            w2[2] = pack2(wlo.z, wlo.z); w2[3] = pack2(wlo.w, wlo.w);
            w2[4] = pack2(whi.x, whi.x); w2[5] = pack2(whi.y, whi.y);
            w2[6] = pack2(whi.z, whi.z); w2[7] = pack2(whi.w, whi.w);
            // X: two LDS.128 -> 4 packed L-pairs
            ulonglong2 q0 = *(const ulonglong2*)&Xs[buf][kk][4 * ty];
            ulonglong2 q1 = *(const ulonglong2*)&Xs[buf][kk][4 * ty + 64];
            ull x2[4] = { q0.x, q0.y, q1.x, q1.y };
            #pragma unroll
            for (int i = 0; i < 4; i++)
                #pragma unroll
                for (int j = 0; j < 8; j++)
                    fma2(acc[i][j], x2[i], w2[j]);
        }
        __syncthreads();
    }

    // ---- epilogue: tanh + score partials over this thread's 8 a's ----
    #pragma unroll
    for (int i = 0; i < 4; i++) {
        float plo = 0.f, phi = 0.f;
        #pragma unroll
        for (int j = 0; j < 8; j++) {
            int a = tx * 8 + j;
            float lo, hi; unpack2(acc[i][j], lo, hi);
            plo += tanhf(lo + u2s[a]) * vs[a];
            phi += tanhf(hi + u2s[a]) * vs[a];
        }
        int l0 = 4 * ty + (i & 1) * 2 + (i >> 1) * 64;
        sp[tx][l0]     = plo;
        sp[tx][l0 + 1] = phi;
    }
    __syncthreads();

    // ---- reduce over 8 a-groups; softmax over L=128 (all 128 threads) ----
    float myscore = 0.f;
    #pragma unroll
    for (int t = 0; t < 8; t++) myscore += sp[t][tid];
    float mval = myscore;
    for (int o = 16; o; o >>= 1) mval = fmaxf(mval, __shfl_xor_sync(0xffffffffu, mval, o));
    if ((tid & 31) == 0) redm[tid >> 5] = mval;
    __syncthreads();
    float m = fmaxf(fmaxf(redm[0], redm[1]), fmaxf(redm[2], redm[3]));
    float e = expf(myscore - m);
    float sv = e;
    for (int o = 16; o; o >>= 1) sv += __shfl_xor_sync(0xffffffffu, sv, o);
    if ((tid & 31) == 0) reds[tid >> 5] = sv;
    __syncthreads();
    float tot = reds[0] + reds[1] + reds[2] + reds[3];
    alpha[tid] = e / tot;
    __syncthreads();

    // ---- z = alpha^T * hidden (float4 coalesced, 150 float4 columns) ----
    for (int d = tid; d < H2_ / 4; d += 128) {
        const float4* h4 = (const float4*)hb + d;
        float4 z = make_float4(0.f, 0.f, 0.f, 0.f);
        #pragma unroll 8
        for (int l = 0; l < L_; l++) {
            float  al = alpha[l];
            float4 hv = h4[l * (H2_ / 4)];
            z.x += al * hv.x; z.y += al * hv.y;
            z.z += al * hv.z; z.w += al * hv.w;
        }
        ((float4*)(out + (size_t)b * H2_))[d] = z;
    }
}

// ---------------------------------------------------------------------------
extern "C" void kernel_launch(void* const* d_in, const int* in_sizes, int n_in,
                              void* d_out, int out_size) {
    const float* hidden = (const float*)d_in[0];
    const float* pos1   = (const float*)d_in[1];
    const float* pos2   = (const float*)d_in[2];
    const int*   e1     = (const int*)d_in[3];
    const int*   e2     = (const int*)d_in[4];
    const float* W_hid  = (const float*)d_in[5];
    const float* W_ent  = (const float*)d_in[6];
    const float* latent = (const float*)d_in[7];
    const float* v      = (const float*)d_in[8];
    float* out = (float*)d_out;

    int B = in_sizes[3];
    k_prep  <<<38, 256>>>(W_ent, latent);
    k_entity<<<B, 256>>>(hidden, e1, e2, W_ent, latent);
    k_main  <<<B, 128>>>(hidden, pos1, pos2, W_hid, v, out);
}